// round 7
// baseline (speedup 1.0000x reference)
#include <cuda_runtime.h>
#include <cuda_bf16.h>
#include <cstdint>

// LaplacianLoss: out[b] = ||w * (L @ x[b])||_F * NV
//   L: [NV, NV] f32 (400 MB, streamed once; mesh Laplacian, band-sparse values)
//   x: [8, NV, 3] f32  -> repacked to X[c][j], c = 3*b + k (24 channels)
//   out: 8 f32
//
// v7 = v6 skeleton with L streamed via LDG.128 (float4 per lane, 512B/warp/
// instr) at the SAME register budget: Lpre[2][6] float4 == 48 regs. Theory:
// in-flight memory is capped by per-instruction tracking entries, so wider
// loads quadruple in-flight bytes. Two-level zero-skip keeps the FMA burst
// rare. k_main placed at local launch index 3 (profiler offset = 2).

#define NVTX     10000
#define NCH      24            // 8 batches * 3 dims
#define JHALF    5000          // j range per grid.y slice
#define JT       256           // j tile staged in smem (= 2 steps of 128 j)
#define RPW      6             // rows per warp
#define WARPS    8
#define ROWS_CTA (WARPS * RPW) // 48
#define NRB      ((NVTX + ROWS_CTA - 1) / ROWS_CTA) // 209
#define PD       2             // pipeline slots (steps of 128 j); == JT/128

typedef unsigned long long ull;

// X repacked as [6][NV] float4: quad q holds channels 4q..4q+3 for vertex j.
__device__ float4 g_X4[6 * NVTX];
// Partial lx: [jh][row][12] f32x2 pairs (pair p = channels 2p, 2p+1).
__device__ ull g_part[2 * NVTX * 12];
// Per-(batch, slice) partial sums.
__device__ float g_red[64];
// Zero-filled float4 landing pad for OOB prefetch addresses (never written).
__device__ float4 g_zero4[32];

#define FFMA2(d, a, b) asm("fma.rn.f32x2 %0, %1, %2, %0;" : "+l"(d) : "l"(a), "l"(b))
#define FADD2(d, a, b) asm("add.rn.f32x2 %0, %1, %2;" : "=l"(d) : "l"(a), "l"(b))
#define PACK2(d, f)    asm("mov.b64 %0, {%1, %1};"     : "=l"(d) : "f"(f))

__device__ __forceinline__ float f4c(const float4& f, int jj) {
    switch (jj) { case 0: return f.x; case 1: return f.y;
                  case 2: return f.z; default: return f.w; }
}

// ---------------------------------------------------------------------------
// Kernel 0: repack x[8][NV][3] -> g_X4[c/4][j].{c%4}
// ---------------------------------------------------------------------------
__global__ void k_buildx(const float* __restrict__ x) {
    int idx = blockIdx.x * blockDim.x + threadIdx.x;   // over NV*24
    if (idx >= NVTX * NCH) return;
    int j = idx / NCH;
    int c = idx - j * NCH;
    int b = c / 3;
    int k = c - 3 * b;
    float v = x[(b * NVTX + j) * 3 + k];
    reinterpret_cast<float*>(g_X4)[(c >> 2) * (NVTX * 4) + j * 4 + (c & 3)] = v;
}

// --- profiler-alignment pads: k_main must be local launch index 3 ---
__global__ void k_pad0(void) {}
__global__ void k_pad1(void) {}

// ---------------------------------------------------------------------------
// Kernel 1: main streaming GEMM. grid = (NRB, 2), block = 256.
//   Lane l loads float4 covering j = step_base + 4l .. 4l+3.
// ---------------------------------------------------------------------------
__global__ void __launch_bounds__(256) k_main(const float* __restrict__ L) {
    // Xs[quad][j%4][j/4]: lane-indexed reads are conflict-free LDS.128.
    __shared__ float4 Xs[6][4][JT / 4];

    const int tid  = threadIdx.x;
    const int lane = tid & 31;
    const int warp = tid >> 5;
    const int jh   = blockIdx.y;
    const int row0 = blockIdx.x * ROWS_CTA + warp * RPW;
    const int jbeg = jh * JHALF;

    // accumulators: 6 rows x 12 channel-pairs (f32x2)
    ull acc[RPW][12];
#pragma unroll
    for (int r = 0; r < RPW; r++)
#pragma unroll
        for (int p = 0; p < 12; p++) acc[r][p] = 0ULL;

    // per-row L base pointers (row-clamped; OOB rows guarded at store time)
    const float* Lp[RPW];
#pragma unroll
    for (int r = 0; r < RPW; r++) {
        int rr = row0 + r;
        if (rr >= NVTX) rr = NVTX - 1;
        Lp[r] = L + (size_t)rr * NVTX + jbeg + 4 * lane;
    }
    const float4* const zp = g_zero4 + lane;

    // depth-PD pipeline of L (steps of 128 j); first 2 steps always in-range
    float4 Lpre[PD][RPW];
#pragma unroll
    for (int q = 0; q < PD; q++)
#pragma unroll
        for (int r = 0; r < RPW; r++)
            Lpre[q][r] = __ldcs(reinterpret_cast<const float4*>(Lp[r] + q * 128));

    const int ntiles = (JHALF + JT - 1) / JT;      // 20

    for (int t = 0; t < ntiles; t++) {
        // stage X tile (zero-padded past JHALF), swizzled layout
        for (int idx = tid; idx < 6 * JT; idx += 256) {
            int p4 = idx >> 8;            // idx / JT
            int jl = idx & (JT - 1);
            int jgl = t * JT + jl;
            float4 v = make_float4(0.f, 0.f, 0.f, 0.f);
            if (jgl < JHALF) v = __ldg(&g_X4[p4 * NVTX + jbeg + jgl]);
            Xs[p4][jl & 3][jl >> 2] = v;
        }
        __syncthreads();

#pragma unroll
        for (int s = 0; s < PD; s++) {
            // ---- zero union over the 6x128 chunk (values loaded a tile ago)
            unsigned u = 0;
#pragma unroll
            for (int r = 0; r < RPW; r++) {
                u |= __float_as_uint(Lpre[s][r].x) | __float_as_uint(Lpre[s][r].y)
                   | __float_as_uint(Lpre[s][r].z) | __float_as_uint(Lpre[s][r].w);
            }

            if (__ballot_sync(0xffffffffu, u != 0u)) {
                const int xb = s * 32 + lane;
#pragma unroll
                for (int jj = 0; jj < 4; jj++) {
                    unsigned uj = 0;
#pragma unroll
                    for (int r = 0; r < RPW; r++)
                        uj |= __float_as_uint(f4c(Lpre[s][r], jj));
                    if (__ballot_sync(0xffffffffu, uj != 0u)) {
                        ull a[RPW];
#pragma unroll
                        for (int r = 0; r < RPW; r++)
                            PACK2(a[r], f4c(Lpre[s][r], jj));
#pragma unroll
                        for (int p4 = 0; p4 < 6; p4++) {
                            ulonglong2 xv = *reinterpret_cast<const ulonglong2*>(
                                &Xs[p4][jj][xb]);
#pragma unroll
                            for (int r = 0; r < RPW; r++) {
                                FFMA2(acc[r][2 * p4 + 0], a[r], xv.x);
                                FFMA2(acc[r][2 * p4 + 1], a[r], xv.y);
                            }
                        }
                    }
                }
            }

            // ---- refill this slot with the SAME step of the NEXT tile.
            // OOB handled on the ADDRESS path (result consumed a tile later).
            {
                int col = (t + 1) * JT + s * 128;
                bool ok = (col + 4 * lane + 3 < JHALF);
#pragma unroll
                for (int r = 0; r < RPW; r++) {
                    const float4* p = ok
                        ? reinterpret_cast<const float4*>(Lp[r] + col) : zp;
                    Lpre[s][r] = __ldcs(p);
                }
            }
        }
        __syncthreads();
    }

    // lane-reduce each (row, pair) across the warp (butterfly, f32x2 adds)
#pragma unroll
    for (int r = 0; r < RPW; r++) {
#pragma unroll
        for (int p = 0; p < 12; p++) {
            ull v = acc[r][p];
#pragma unroll
            for (int m = 16; m >= 1; m >>= 1) {
                ull o = __shfl_xor_sync(0xffffffffu, v, m);
                ull s;
                FADD2(s, v, o);
                v = s;
            }
            acc[r][p] = v;
        }
    }

    if (lane == 0) {
#pragma unroll
        for (int r = 0; r < RPW; r++) {
            int row = row0 + r;
            if (row < NVTX) {
#pragma unroll
                for (int p = 0; p < 12; p++)
                    g_part[((size_t)jh * NVTX + row) * 12 + p] = acc[r][p];
            }
        }
    }
}

// ---------------------------------------------------------------------------
// Kernel 2: partial sum-of-squares. grid = 64 (8 batches x 8 row slices).
// ---------------------------------------------------------------------------
__global__ void k_partial(void) {
    const int b  = blockIdx.x >> 3;
    const int sl = blockIdx.x & 7;
    const int tid = threadIdx.x;
    __shared__ float red[256];

    const float* P = reinterpret_cast<const float*>(g_part); // [jh][row][24]
    const int i0 = sl * (NVTX / 8);
    const int i1 = i0 + (NVTX / 8);

    float s = 0.f;
    for (int idx = i0 * 3 + tid; idx < i1 * 3; idx += 256) {
        int i = idx / 3;
        int k = idx - 3 * i;
        int c = 3 * b + k;
        float v = P[(size_t)i * 24 + c] + P[((size_t)NVTX + i) * 24 + c];
        s += v * v;
    }
    red[tid] = s;
    __syncthreads();
    for (int off = 128; off > 0; off >>= 1) {
        if (tid < off) red[tid] += red[tid + off];
        __syncthreads();
    }
    if (tid == 0) g_red[blockIdx.x] = red[0];
}

// ---------------------------------------------------------------------------
// Kernel 3: finalize. 1 block, 64 threads.
// ---------------------------------------------------------------------------
__global__ void k_final(const float* __restrict__ w, float* __restrict__ out) {
    __shared__ float sh[64];
    int t = threadIdx.x;
    sh[t] = g_red[t];
    __syncthreads();
    if (t < 8) {
        float s = 0.f;
#pragma unroll
        for (int j = 0; j < 8; j++) s += sh[t * 8 + j];
        out[t] = w[0] * (float)NVTX * sqrtf(s);
    }
}

// ---------------------------------------------------------------------------
extern "C" void kernel_launch(void* const* d_in, const int* in_sizes, int n_in,
                              void* d_out, int out_size) {
    const float* x = nullptr;
    const float* L = nullptr;
    const float* w = nullptr;
    for (int i = 0; i < n_in; i++) {
        if (in_sizes[i] == 8 * NVTX * 3)          x = (const float*)d_in[i];
        else if (in_sizes[i] == NVTX * NVTX)      L = (const float*)d_in[i];
        else if (in_sizes[i] == 1)                w = (const float*)d_in[i];
    }
    float* out = (float*)d_out;

    k_buildx<<<(NVTX * NCH + 255) / 256, 256>>>(x);   // local 0 (global 2)
    k_pad0<<<1, 32>>>();                               // local 1
    k_pad1<<<1, 32>>>();                               // local 2
    dim3 grid(NRB, 2);
    k_main<<<grid, 256>>>(L);                          // local 3 (global 5) <- ncu
    k_partial<<<64, 256>>>();
    k_final<<<1, 64>>>(w, out);
}